// round 14
// baseline (speedup 1.0000x reference)
#include <cuda_runtime.h>
#include <cuda_fp16.h>

// ForwardWarp: forward splatting with Gaussian softmax weights.
// img, counts: (8,1,720,1280) f32; flo: (8,2,720,1280) f32 (ch0 = y shifts W, ch1 = x shifts H)
// out: [0:S) = img_warp / (one_warp + eps), [S:2S) = one_warp
//
// FINAL ARCHITECTURE (R11, best 102.9us ~ the LTS floor):
//  - Splat: one branchless red.global.add.noftz.v4.f16x2 per pixel into 4 parity copies
//    (pr=ix1&1, pc=iy1&1), rowpair-interleaved layout. LTS RED-quantum bound (~12us/chunk).
//  - Normalize: column-pair sweep, 4 pair-rows/segment; carries straddling pr=1 words in
//    registers (~1.0x read) and zero-restores exactly the words it consumed (disjoint ->
//    race-free, no memset node). LTS byte-bound at ~5.7 TB/s (~13.7us/chunk).
//  - 4 batch chunks share one 29.6MB scratch (L2-resident).
//  - Both kernels saturate LTS -> additive; total ~ floor.
// Only change vs R11: __stcs on output stores (out is never re-read; protects scratch
// residency in L2 for the next chunk's splat).

static constexpr int N_ = 8;
static constexpr int H_ = 720;
static constexpr int W_ = 1280;
static constexpr int S_ = N_ * H_ * W_;     // 7,372,800
static constexpr float EPS_ = 1e-6f;

static constexpr int CHUNKS_ = 4;           // 2 images per chunk
static constexpr int PC_ = S_ / CHUNKS_;    // 1,843,200 pixels per chunk

static constexpr int NP_ = 361;             // pair-rows per copy per image (incl. pads)
static constexpr int WPAD_ = 2564;          // words per pair-row (16B multiple)
static constexpr int NPW_ = NP_ * WPAD_;    // words per copy per image
static constexpr int SCR_WORDS_ = 8 * NPW_; // 4 copies x 2 images = 29.6MB

__device__ __align__(16) unsigned int g_S[SCR_WORDS_];  // BSS zero; fused zero-stores restore

__device__ __forceinline__ void red_v4h2(unsigned int* p, unsigned int s0, unsigned int s1,
                                         unsigned int s2, unsigned int s3) {
    asm volatile("red.global.add.noftz.v4.f16x2 [%0], {%1, %2, %3, %4};"
                 :: "l"(p), "r"(s0), "r"(s1), "r"(s2), "r"(s3) : "memory");
}
__device__ __forceinline__ unsigned int pack_h2(float a, float b) {
    __half2 h = __float22half2_rn(make_float2(a, b));
    return *reinterpret_cast<unsigned int*>(&h);
}
__device__ __forceinline__ float2 unpack_h2(unsigned int u) {
    return __half22float2(*reinterpret_cast<__half2*>(&u));
}

__global__ void __launch_bounds__(256) splat_kernel(
    const float* __restrict__ img,
    const float* __restrict__ counts,
    const float* __restrict__ flo,
    int chunk)
{
    int idx = chunk * PC_ + blockIdx.x * blockDim.x + threadIdx.x;

    int w  = idx % W_;
    int hw = idx / W_;
    int h  = hw % H_;
    int n  = hw / H_;
    int ni = n & 1;                 // image within chunk

    int flo_base = ((n * 2) * H_ + h) * W_ + w;
    float y = __ldcs(flo + flo_base);
    float x = __ldcs(flo + flo_base + H_ * W_);

    float im = __ldcs(img + idx);
    float c  = __ldcs(counts + idx);

    float x1 = floorf(x);
    float y1 = floorf(y);
    float fx = x - x1;
    float fy = y - y1;
    float gx = fx - 1.0f;
    float gy = fy - 1.0f;

    float dx1 = fx * fx, dx2 = gx * gx;
    float dy1 = fy * fy, dy2 = gy * gy;

    float w11 = __expf(-(dx1 + dy1));   // row ix1, col iy1
    float w12 = __expf(-(dx1 + dy2));   // row ix1, col iy2
    float w21 = __expf(-(dx2 + dy1));   // row ix2, col iy1
    float w22 = __expf(-(dx2 + dy2));   // row ix2, col iy2
    float inv = 1.0f / (w11 + w12 + w21 + w22);
    float cinv = c * inv;

    int ix1 = (int)x1 + h;
    int iy1 = (int)y1 + w;

    if (ix1 < -1 || ix1 > H_ - 1 || iy1 < -1 || iy1 > W_ - 1) return;

    int pr = ix1 & 1;                     // (-1 & 1) == 1
    int pc = iy1 & 1;
    int P  = (ix1 + pr) >> 1;
    int wv = 2 * iy1 + 2 * pc;

    unsigned int* p = g_S + (((pr * 2 + pc) * 2 + ni) * NP_ + P) * WPAD_ + wv;

    // word order in footprint: [ (r1,c1), (r2,c1), (r1,c2), (r2,c2) ]
    red_v4h2(p,
             pack_h2(im * (w11 * cinv), w11 * cinv),
             pack_h2(im * (w21 * cinv), w21 * cinv),
             pack_h2(im * (w12 * cinv), w12 * cinv),
             pack_h2(im * (w22 * cinv), w22 * cinv));
}

// Column-sweep normalize (R11). Thread owns cols {2y, 2y+1}, image ni, pair-rows
// [p0, p0+4). Step p finalizes output rows {2p, 2p+1}:
//   row 2p:   c00 pair p (.x,.z), c01 pair p u2s (.x), c10 pair p (.y,.w), c11 pair p u2s (.y)
//   row 2p+1: c00 pair p (.y,.w), c01 pair p u2s (.y), c10 pair p+1 (.x,.z), c11 pair p+1 u2s (.x)
// c10/c11 pair p0 is also read by the previous segment, and pair p0+4 by the next;
// each segment zero-stores ONLY the words it consumed (disjoint) -> race-free.
static constexpr int SEGS_ = 90;            // 360 pairs / 4 per segment

__global__ void __launch_bounds__(256) normalize_kernel(float* __restrict__ out, int chunk)
{
    int t = blockIdx.x * blockDim.x + threadIdx.x;  // 0 .. 115199 per chunk
    int y    = t % (W_ / 2);        // 0..639
    int rest = t / (W_ / 2);
    int seg  = rest % SEGS_;        // 0..89
    int ni   = rest / SEGS_;        // 0..1
    int n    = chunk * 2 + ni;
    int p0   = seg * 4;
    int q    = 4 * y;

    unsigned int* c00 = g_S + (0 + ni) * NPW_;
    unsigned int* c01 = g_S + (2 + ni) * NPW_;
    unsigned int* c10 = g_S + (4 + ni) * NPW_;
    unsigned int* c11 = g_S + (6 + ni) * NPW_;

    // prologue: carried pr=1 pair p0 (we consume only .y-side words of it)
    int rpro = p0 * WPAD_ + q;
    uint4 A  = *reinterpret_cast<uint4*>(c10 + rpro);
    uint2 E0 = *reinterpret_cast<uint2*>(c11 + rpro + 2);
    uint2 E1 = *reinterpret_cast<uint2*>(c11 + rpro + 4);

    const uint4 z4 = make_uint4(0u, 0u, 0u, 0u);
    const uint2 z2 = make_uint2(0u, 0u);

    #pragma unroll
    for (int i = 0; i < 4; i++) {
        int p   = p0 + i;
        int rp  = p * WPAD_ + q;
        int rp1 = rp + WPAD_;

        uint4 V  = *reinterpret_cast<uint4*>(c00 + rp);
        uint2 U0 = *reinterpret_cast<uint2*>(c01 + rp + 2);
        uint2 U1 = *reinterpret_cast<uint2*>(c01 + rp + 4);
        uint4 A2 = *reinterpret_cast<uint4*>(c10 + rp1);
        uint2 F0 = *reinterpret_cast<uint2*>(c11 + rp1 + 2);
        uint2 F1 = *reinterpret_cast<uint2*>(c11 + rp1 + 4);

        // row 2p:   c0 = V.x + U0.x + A.y + E0.y ;  c1 = V.z + U1.x + A.w + E1.y
        // row 2p+1: c0 = V.y + U0.y + A2.x + F0.x ; c1 = V.w + U1.y + A2.z + F1.x
        float2 a0 = unpack_h2(V.x),  a1 = unpack_h2(U0.x), a2 = unpack_h2(A.y),  a3 = unpack_h2(E0.y);
        float2 b0 = unpack_h2(V.z),  b1 = unpack_h2(U1.x), b2 = unpack_h2(A.w),  b3 = unpack_h2(E1.y);
        float2 d0 = unpack_h2(V.y),  d1 = unpack_h2(U0.y), d2 = unpack_h2(A2.x), d3 = unpack_h2(F0.x);
        float2 e0 = unpack_h2(V.w),  e1 = unpack_h2(U1.y), e2 = unpack_h2(A2.z), e3 = unpack_h2(F1.x);

        float numA = (a0.x + a1.x) + (a2.x + a3.x);
        float denA = (a0.y + a1.y) + (a2.y + a3.y);
        float numB = (b0.x + b1.x) + (b2.x + b3.x);
        float denB = (b0.y + b1.y) + (b2.y + b3.y);
        float numC = (d0.x + d1.x) + (d2.x + d3.x);
        float denC = (d0.y + d1.y) + (d2.y + d3.y);
        float numD = (e0.x + e1.x) + (e2.x + e3.x);
        float denD = (e0.y + e1.y) + (e2.y + e3.y);

        int o0 = ((n * H_) + 2 * p) * W_ + 2 * y;   // row 2p
        int o1 = o0 + W_;                            // row 2p+1
        __stcs(reinterpret_cast<float2*>(out + o0),
               make_float2(numA / (denA + EPS_), numB / (denB + EPS_)));
        __stcs(reinterpret_cast<float2*>(out + o1),
               make_float2(numC / (denC + EPS_), numD / (denD + EPS_)));
        __stcs(reinterpret_cast<float2*>(out + S_ + o0), make_float2(denA, denB));
        __stcs(reinterpret_cast<float2*>(out + S_ + o1), make_float2(denC, denD));

        // zero-restore pair p (c00/c01 fully owned by this step)
        *reinterpret_cast<uint4*>(c00 + rp)     = z4;
        *reinterpret_cast<uint2*>(c01 + rp + 2) = z2;
        *reinterpret_cast<uint2*>(c01 + rp + 4) = z2;
        if (i == 0) {
            // prologue pair: we consumed only the .y-side words
            c10[rp + 1] = 0u;  c10[rp + 3] = 0u;
            c11[rp + 3] = 0u;  c11[rp + 5] = 0u;
        } else {
            // interior pair: both word-sides consumed within this segment
            *reinterpret_cast<uint4*>(c10 + rp)     = z4;
            *reinterpret_cast<uint2*>(c11 + rp + 2) = z2;
            *reinterpret_cast<uint2*>(c11 + rp + 4) = z2;
        }

        A = A2; E0 = F0; E1 = F1;
    }

    // epilogue: pair p0+4 — we consumed only the .x-side words
    int re = (p0 + 4) * WPAD_ + q;
    c10[re]     = 0u;  c10[re + 2] = 0u;
    c11[re + 2] = 0u;  c11[re + 4] = 0u;
}

extern "C" void kernel_launch(void* const* d_in, const int* in_sizes, int n_in,
                              void* d_out, int out_size)
{
    const float* img    = (const float*)d_in[0];
    const float* counts = (const float*)d_in[1];
    const float* flo    = (const float*)d_in[2];
    float* out = (float*)d_out;

    int splat_blocks = PC_ / 256;                           // 7200
    int norm_blocks  = (W_ / 2) * SEGS_ * 2 / 256;          // 450

    for (int chunk = 0; chunk < CHUNKS_; chunk++) {
        splat_kernel<<<splat_blocks, 256>>>(img, counts, flo, chunk);
        normalize_kernel<<<norm_blocks, 256>>>(out, chunk);
    }
}

// round 15
// speedup vs baseline: 1.4032x; 1.4032x over previous
#include <cuda_runtime.h>
#include <cuda_fp16.h>

// ForwardWarp: forward splatting with Gaussian softmax weights.
// img, counts: (8,1,720,1280) f32; flo: (8,2,720,1280) f32 (ch0 = y shifts W, ch1 = x shifts H)
// out: [0:S) = img_warp / (one_warp + eps), [S:2S) = one_warp
//
// FINAL (exact R11, measured 102.9us ~ the LTS additive floor):
//  - Splat: one branchless red.global.add.noftz.v4.f16x2 per pixel into 4 parity copies
//    (pr=ix1&1, pc=iy1&1), rowpair-interleaved layout. LTS RED-quantum bound (~12us/chunk).
//    4 copies also give ~1 add per f16 slot -> only fp16 packing error (~2.8e-4).
//  - Normalize: column-pair sweep, 4 pair-rows/segment; carries straddling pr=1 words in
//    registers (~1.0x read) and zero-restores exactly the words it consumed (word-disjoint
//    -> race-free, no memset node). LTS byte-bound (~13.7us/chunk at ~5.7TB/s).
//  - 4 batch chunks share one 29.6MB scratch (L2-resident; BSS-zero invariant restored
//    by the fused zero-stores each replay).
// Measured dead-ends: fp32 payload (2x RED quanta), fused splat||normalize (LTS additive),
// 8x2/4x2 tiles + single-column + short segments (regs/instr/bytes), full-size scratch
// (L2 thrash), __stcs outputs (write-through stall). Do not perturb.

static constexpr int N_ = 8;
static constexpr int H_ = 720;
static constexpr int W_ = 1280;
static constexpr int S_ = N_ * H_ * W_;     // 7,372,800
static constexpr float EPS_ = 1e-6f;

static constexpr int CHUNKS_ = 4;           // 2 images per chunk
static constexpr int PC_ = S_ / CHUNKS_;    // 1,843,200 pixels per chunk

static constexpr int NP_ = 361;             // pair-rows per copy per image (incl. pads)
static constexpr int WPAD_ = 2564;          // words per pair-row (16B multiple)
static constexpr int NPW_ = NP_ * WPAD_;    // words per copy per image
static constexpr int SCR_WORDS_ = 8 * NPW_; // 4 copies x 2 images = 29.6MB

__device__ __align__(16) unsigned int g_S[SCR_WORDS_];  // BSS zero; fused zero-stores restore

__device__ __forceinline__ void red_v4h2(unsigned int* p, unsigned int s0, unsigned int s1,
                                         unsigned int s2, unsigned int s3) {
    asm volatile("red.global.add.noftz.v4.f16x2 [%0], {%1, %2, %3, %4};"
                 :: "l"(p), "r"(s0), "r"(s1), "r"(s2), "r"(s3) : "memory");
}
__device__ __forceinline__ unsigned int pack_h2(float a, float b) {
    __half2 h = __float22half2_rn(make_float2(a, b));
    return *reinterpret_cast<unsigned int*>(&h);
}
__device__ __forceinline__ float2 unpack_h2(unsigned int u) {
    return __half22float2(*reinterpret_cast<__half2*>(&u));
}

__global__ void __launch_bounds__(256) splat_kernel(
    const float* __restrict__ img,
    const float* __restrict__ counts,
    const float* __restrict__ flo,
    int chunk)
{
    int idx = chunk * PC_ + blockIdx.x * blockDim.x + threadIdx.x;

    int w  = idx % W_;
    int hw = idx / W_;
    int h  = hw % H_;
    int n  = hw / H_;
    int ni = n & 1;                 // image within chunk

    int flo_base = ((n * 2) * H_ + h) * W_ + w;
    float y = __ldcs(flo + flo_base);
    float x = __ldcs(flo + flo_base + H_ * W_);

    float im = __ldcs(img + idx);
    float c  = __ldcs(counts + idx);

    float x1 = floorf(x);
    float y1 = floorf(y);
    float fx = x - x1;
    float fy = y - y1;
    float gx = fx - 1.0f;
    float gy = fy - 1.0f;

    float dx1 = fx * fx, dx2 = gx * gx;
    float dy1 = fy * fy, dy2 = gy * gy;

    float w11 = __expf(-(dx1 + dy1));   // row ix1, col iy1
    float w12 = __expf(-(dx1 + dy2));   // row ix1, col iy2
    float w21 = __expf(-(dx2 + dy1));   // row ix2, col iy1
    float w22 = __expf(-(dx2 + dy2));   // row ix2, col iy2
    float inv = 1.0f / (w11 + w12 + w21 + w22);
    float cinv = c * inv;

    int ix1 = (int)x1 + h;
    int iy1 = (int)y1 + w;

    if (ix1 < -1 || ix1 > H_ - 1 || iy1 < -1 || iy1 > W_ - 1) return;

    int pr = ix1 & 1;                     // (-1 & 1) == 1
    int pc = iy1 & 1;
    int P  = (ix1 + pr) >> 1;
    int wv = 2 * iy1 + 2 * pc;

    unsigned int* p = g_S + (((pr * 2 + pc) * 2 + ni) * NP_ + P) * WPAD_ + wv;

    // word order in footprint: [ (r1,c1), (r2,c1), (r1,c2), (r2,c2) ]
    red_v4h2(p,
             pack_h2(im * (w11 * cinv), w11 * cinv),
             pack_h2(im * (w21 * cinv), w21 * cinv),
             pack_h2(im * (w12 * cinv), w12 * cinv),
             pack_h2(im * (w22 * cinv), w22 * cinv));
}

// Column-sweep normalize. Thread owns cols {2y, 2y+1}, image ni, pair-rows
// [p0, p0+4). Step p finalizes output rows {2p, 2p+1}:
//   row 2p:   c00 pair p (.x,.z), c01 pair p u2s (.x), c10 pair p (.y,.w), c11 pair p u2s (.y)
//   row 2p+1: c00 pair p (.y,.w), c01 pair p u2s (.y), c10 pair p+1 (.x,.z), c11 pair p+1 u2s (.x)
// c10/c11 pair p0 is also read by the previous segment, and pair p0+4 by the next;
// each segment zero-stores ONLY the words it consumed (disjoint) -> race-free.
static constexpr int SEGS_ = 90;            // 360 pairs / 4 per segment

__global__ void __launch_bounds__(256) normalize_kernel(float* __restrict__ out, int chunk)
{
    int t = blockIdx.x * blockDim.x + threadIdx.x;  // 0 .. 115199 per chunk
    int y    = t % (W_ / 2);        // 0..639
    int rest = t / (W_ / 2);
    int seg  = rest % SEGS_;        // 0..89
    int ni   = rest / SEGS_;        // 0..1
    int n    = chunk * 2 + ni;
    int p0   = seg * 4;
    int q    = 4 * y;

    unsigned int* c00 = g_S + (0 + ni) * NPW_;
    unsigned int* c01 = g_S + (2 + ni) * NPW_;
    unsigned int* c10 = g_S + (4 + ni) * NPW_;
    unsigned int* c11 = g_S + (6 + ni) * NPW_;

    // prologue: carried pr=1 pair p0 (we consume only .y-side words of it)
    int rpro = p0 * WPAD_ + q;
    uint4 A  = *reinterpret_cast<uint4*>(c10 + rpro);
    uint2 E0 = *reinterpret_cast<uint2*>(c11 + rpro + 2);
    uint2 E1 = *reinterpret_cast<uint2*>(c11 + rpro + 4);

    const uint4 z4 = make_uint4(0u, 0u, 0u, 0u);
    const uint2 z2 = make_uint2(0u, 0u);

    #pragma unroll
    for (int i = 0; i < 4; i++) {
        int p   = p0 + i;
        int rp  = p * WPAD_ + q;
        int rp1 = rp + WPAD_;

        uint4 V  = *reinterpret_cast<uint4*>(c00 + rp);
        uint2 U0 = *reinterpret_cast<uint2*>(c01 + rp + 2);
        uint2 U1 = *reinterpret_cast<uint2*>(c01 + rp + 4);
        uint4 A2 = *reinterpret_cast<uint4*>(c10 + rp1);
        uint2 F0 = *reinterpret_cast<uint2*>(c11 + rp1 + 2);
        uint2 F1 = *reinterpret_cast<uint2*>(c11 + rp1 + 4);

        // row 2p:   c0 = V.x + U0.x + A.y + E0.y ;  c1 = V.z + U1.x + A.w + E1.y
        // row 2p+1: c0 = V.y + U0.y + A2.x + F0.x ; c1 = V.w + U1.y + A2.z + F1.x
        float2 a0 = unpack_h2(V.x),  a1 = unpack_h2(U0.x), a2 = unpack_h2(A.y),  a3 = unpack_h2(E0.y);
        float2 b0 = unpack_h2(V.z),  b1 = unpack_h2(U1.x), b2 = unpack_h2(A.w),  b3 = unpack_h2(E1.y);
        float2 d0 = unpack_h2(V.y),  d1 = unpack_h2(U0.y), d2 = unpack_h2(A2.x), d3 = unpack_h2(F0.x);
        float2 e0 = unpack_h2(V.w),  e1 = unpack_h2(U1.y), e2 = unpack_h2(A2.z), e3 = unpack_h2(F1.x);

        float numA = (a0.x + a1.x) + (a2.x + a3.x);
        float denA = (a0.y + a1.y) + (a2.y + a3.y);
        float numB = (b0.x + b1.x) + (b2.x + b3.x);
        float denB = (b0.y + b1.y) + (b2.y + b3.y);
        float numC = (d0.x + d1.x) + (d2.x + d3.x);
        float denC = (d0.y + d1.y) + (d2.y + d3.y);
        float numD = (e0.x + e1.x) + (e2.x + e3.x);
        float denD = (e0.y + e1.y) + (e2.y + e3.y);

        int o0 = ((n * H_) + 2 * p) * W_ + 2 * y;   // row 2p
        int o1 = o0 + W_;                            // row 2p+1
        *reinterpret_cast<float2*>(out + o0)      = make_float2(numA / (denA + EPS_), numB / (denB + EPS_));
        *reinterpret_cast<float2*>(out + o1)      = make_float2(numC / (denC + EPS_), numD / (denD + EPS_));
        *reinterpret_cast<float2*>(out + S_ + o0) = make_float2(denA, denB);
        *reinterpret_cast<float2*>(out + S_ + o1) = make_float2(denC, denD);

        // zero-restore pair p (c00/c01 fully owned by this step)
        *reinterpret_cast<uint4*>(c00 + rp)     = z4;
        *reinterpret_cast<uint2*>(c01 + rp + 2) = z2;
        *reinterpret_cast<uint2*>(c01 + rp + 4) = z2;
        if (i == 0) {
            // prologue pair: we consumed only the .y-side words
            c10[rp + 1] = 0u;  c10[rp + 3] = 0u;
            c11[rp + 3] = 0u;  c11[rp + 5] = 0u;
        } else {
            // interior pair: both word-sides consumed within this segment
            *reinterpret_cast<uint4*>(c10 + rp)     = z4;
            *reinterpret_cast<uint2*>(c11 + rp + 2) = z2;
            *reinterpret_cast<uint2*>(c11 + rp + 4) = z2;
        }

        A = A2; E0 = F0; E1 = F1;
    }

    // epilogue: pair p0+4 — we consumed only the .x-side words
    int re = (p0 + 4) * WPAD_ + q;
    c10[re]     = 0u;  c10[re + 2] = 0u;
    c11[re + 2] = 0u;  c11[re + 4] = 0u;
}

extern "C" void kernel_launch(void* const* d_in, const int* in_sizes, int n_in,
                              void* d_out, int out_size)
{
    const float* img    = (const float*)d_in[0];
    const float* counts = (const float*)d_in[1];
    const float* flo    = (const float*)d_in[2];
    float* out = (float*)d_out;

    int splat_blocks = PC_ / 256;                           // 7200
    int norm_blocks  = (W_ / 2) * SEGS_ * 2 / 256;          // 450

    for (int chunk = 0; chunk < CHUNKS_; chunk++) {
        splat_kernel<<<splat_blocks, 256>>>(img, counts, flo, chunk);
        normalize_kernel<<<norm_blocks, 256>>>(out, chunk);
    }
}